// round 4
// baseline (speedup 1.0000x reference)
#include <cuda_runtime.h>
#include <cuda_bf16.h>
#include <math.h>

// Problem constants (match reference)
#define NN 50000
#define NE 800000
#define IN_F 256
#define D1 128      // HEADS*HID
#define OUT_F 64
#define SLOPE 0.2f

// ---------------- device scratch (no allocations allowed) ----------------
__device__ __align__(16) float g_h[(size_t)NN * D1];     // GEMM output / layer features
__device__ __align__(16) float g_act[(size_t)NN * D1];   // post-aggregate activations
__device__ __align__(16) float g_als[(size_t)NN * 4];
__device__ __align__(16) float g_ald[(size_t)NN * 4];
__device__ int   g_rowptr[NN + 1];
__device__ int   g_deg[NN];
__device__ int   g_cursor[NN];
__device__ int   g_csr_src[NE];
__device__ float g_csr_w[NE];
__device__ int   g_idx64;   // 1 if edge_index is int64, 0 if int32

// ---------------- edge-index dtype detection ----------------
__global__ void k_detect_idx(const void* ei_raw, int E) {
    // Single thread: interpret first entries as int64; if all in [0,NN) -> int64.
    if (threadIdx.x == 0 && blockIdx.x == 0) {
        const long long* p = (const long long*)ei_raw;
        int nchk = 2 * E < 1024 ? 2 * E : 1024;
        int ok = 1;
        for (int i = 0; i < nchk; i++) {
            long long v = p[i];
            if (v < 0 || v >= NN) { ok = 0; break; }
        }
        g_idx64 = ok;
    }
}

__device__ __forceinline__ void load_edge(const void* ei_raw, int E, int e, int idx64,
                                          int& s, int& d) {
    if (idx64) {
        const long long* p = (const long long*)ei_raw;
        s = (int)p[e];
        d = (int)p[E + e];
    } else {
        const int* p = (const int*)ei_raw;
        s = p[e];
        d = p[E + e];
    }
}

// ---------------- CSR construction ----------------
__global__ void k_zero_deg(int n) {
    int i = blockIdx.x * blockDim.x + threadIdx.x;
    if (i < n) g_deg[i] = 0;
}

__global__ void k_count_deg(const void* ei_raw, int E, int n) {
    int e = blockIdx.x * blockDim.x + threadIdx.x;
    int idx64 = g_idx64;
    if (e < E) {
        int s, d;
        load_edge(ei_raw, E, e, idx64, s, d);
        if (d >= 0 && d < n) atomicAdd(&g_deg[d], 1);
    }
}

__global__ void k_scan_deg(int n) {
    __shared__ int s[1024];
    int t = threadIdx.x;
    if (t == 0) g_rowptr[0] = 0;
    int carry = 0;
    for (int base = 0; base < n; base += 1024) {
        int v = (base + t < n) ? g_deg[base + t] : 0;
        s[t] = v;
        __syncthreads();
        for (int off = 1; off < 1024; off <<= 1) {
            int tmp = (t >= off) ? s[t - off] : 0;
            __syncthreads();
            s[t] += tmp;
            __syncthreads();
        }
        if (base + t < n) g_rowptr[base + t + 1] = carry + s[t];
        carry += s[1023];
        __syncthreads();
    }
}

__global__ void k_copy_cursor(int n) {
    int i = blockIdx.x * blockDim.x + threadIdx.x;
    if (i < n) g_cursor[i] = g_rowptr[i];
}

__global__ void k_scatter(const void* ei_raw, const float* __restrict__ ew, int E, int n) {
    int e = blockIdx.x * blockDim.x + threadIdx.x;
    int idx64 = g_idx64;
    if (e < E) {
        int s, d;
        load_edge(ei_raw, E, e, idx64, s, d);
        if (s >= 0 && s < n && d >= 0 && d < n) {
            int pos = atomicAdd(&g_cursor[d], 1);
            if (pos >= 0 && pos < E) {
                g_csr_src[pos] = s;
                g_csr_w[pos] = ew[e];
            }
        }
    }
}

// ---------------- SGEMM: g_h[M,Nc] = A[M,K] @ B[K,Nc] ----------------
// A = Aext if non-null else g_act. BM=128, BN=64, BK=16, TM=8, TN=4, 256 thr.
__global__ __launch_bounds__(256, 2)
void k_sgemm(const float* __restrict__ Aext, const float* __restrict__ B,
             int M, int K, int Nc) {
    constexpr int BM = 128, BN = 64, BK = 16, TM = 8, TN = 4;
    __shared__ __align__(16) float As[BK][BM];
    __shared__ __align__(16) float Bs[BK][BN];

    const float* __restrict__ A = Aext ? Aext : g_act;
    float* __restrict__ C = g_h;

    int tid = threadIdx.x;
    int tx = tid & 15;   // col group
    int ty = tid >> 4;   // row group
    int bm0 = blockIdx.y * BM;
    int bn0 = blockIdx.x * BN;

    int rA = tid >> 2;          // 0..63
    int kA = (tid & 3) * 4;     // 0,4,8,12
    int kB = tid >> 4;          // 0..15
    int nB = (tid & 15) * 4;    // 0..60

    float acc[TM][TN];
#pragma unroll
    for (int i = 0; i < TM; i++)
#pragma unroll
        for (int j = 0; j < TN; j++) acc[i][j] = 0.f;

    for (int k0 = 0; k0 < K; k0 += BK) {
#pragma unroll
        for (int it = 0; it < 2; it++) {
            int r = rA + it * 64;
            int grow = bm0 + r;
            float4 v = make_float4(0.f, 0.f, 0.f, 0.f);
            if (grow < M) v = *(const float4*)(A + (size_t)grow * K + k0 + kA);
            As[kA + 0][r] = v.x; As[kA + 1][r] = v.y;
            As[kA + 2][r] = v.z; As[kA + 3][r] = v.w;
        }
        {
            float4 v = *(const float4*)(B + (size_t)(k0 + kB) * Nc + bn0 + nB);
            *(float4*)&Bs[kB][nB] = v;
        }
        __syncthreads();
#pragma unroll
        for (int kk = 0; kk < BK; kk++) {
            float a[TM], b[TN];
#pragma unroll
            for (int i = 0; i < TM; i++) a[i] = As[kk][ty * TM + i];
#pragma unroll
            for (int j = 0; j < TN; j++) b[j] = Bs[kk][tx * TN + j];
#pragma unroll
            for (int i = 0; i < TM; i++)
#pragma unroll
                for (int j = 0; j < TN; j++) acc[i][j] = fmaf(a[i], b[j], acc[i][j]);
        }
        __syncthreads();
    }
#pragma unroll
    for (int i = 0; i < TM; i++) {
        int grow = bm0 + ty * TM + i;
        if (grow < M) {
            float4 v = make_float4(acc[i][0], acc[i][1], acc[i][2], acc[i][3]);
            *(float4*)(C + (size_t)grow * Nc + bn0 + tx * TN) = v;
        }
    }
}

// ---------------- attention dot products: g_als/g_ald [N,H] ----------------
template <int H, int C>
__global__ void k_dots(const float* __restrict__ a_src, const float* __restrict__ a_dst, int n) {
    constexpr int D = H * C;
    constexpr int CPL = D / 32;     // channels per lane
    constexpr int G = 32 / H;       // lanes per head
    int wid = threadIdx.x >> 5;
    int lane = threadIdx.x & 31;
    int node = blockIdx.x * 4 + wid;
    if (node >= n) return;
    int c0 = lane * CPL;
    float ss = 0.f, sd = 0.f;
    const float* hr = g_h + (size_t)node * D;
#pragma unroll
    for (int j = 0; j < CPL; j++) {
        float hv = hr[c0 + j];
        ss = fmaf(hv, a_src[c0 + j], ss);
        sd = fmaf(hv, a_dst[c0 + j], sd);
    }
#pragma unroll
    for (int o = G / 2; o > 0; o >>= 1) {
        ss += __shfl_down_sync(0xffffffffu, ss, o, G);
        sd += __shfl_down_sync(0xffffffffu, sd, o, G);
    }
    if ((lane % G) == 0) {
        int hd = lane / G;
        g_als[(size_t)node * H + hd] = ss;
        g_ald[(size_t)node * H + hd] = sd;
    }
}

// ---------------- fused segment softmax + weighted aggregate ----------------
template <int H, int C, bool RELU>
__global__ void k_aggregate(const float* __restrict__ bias, float* __restrict__ outExt, int n) {
    constexpr int D = H * C;
    constexpr int CPL = D / 32;
    constexpr int G = 32 / H;
    float* __restrict__ out = outExt ? outExt : g_act;
    int wid = threadIdx.x >> 5;
    int lane = threadIdx.x & 31;
    int node = blockIdx.x * 4 + wid;
    if (node >= n) return;

    int s0 = g_rowptr[node];
    int s1 = g_rowptr[node + 1];

    float aldn[H];
#pragma unroll
    for (int hh = 0; hh < H; hh++) aldn[hh] = g_ald[(size_t)node * H + hh];

    // pass 1: per-head max of leaky logits
    float mx[H];
#pragma unroll
    for (int hh = 0; hh < H; hh++) mx[hh] = -1e30f;
    for (int i = s0 + lane; i < s1; i += 32) {
        int s = g_csr_src[i];
#pragma unroll
        for (int hh = 0; hh < H; hh++) {
            float l = g_als[(size_t)s * H + hh] + aldn[hh];
            l = (l > 0.f) ? l : SLOPE * l;
            mx[hh] = fmaxf(mx[hh], l);
        }
    }
#pragma unroll
    for (int hh = 0; hh < H; hh++)
#pragma unroll
        for (int o = 16; o > 0; o >>= 1)
            mx[hh] = fmaxf(mx[hh], __shfl_xor_sync(0xffffffffu, mx[hh], o));

    // pass 2: denom
    float sm[H];
#pragma unroll
    for (int hh = 0; hh < H; hh++) sm[hh] = 0.f;
    for (int i = s0 + lane; i < s1; i += 32) {
        int s = g_csr_src[i];
        float w = g_csr_w[i];
#pragma unroll
        for (int hh = 0; hh < H; hh++) {
            float l = g_als[(size_t)s * H + hh] + aldn[hh];
            l = (l > 0.f) ? l : SLOPE * l;
            sm[hh] += __expf(l - mx[hh]) * w;
        }
    }
#pragma unroll
    for (int hh = 0; hh < H; hh++)
#pragma unroll
        for (int o = 16; o > 0; o >>= 1)
            sm[hh] += __shfl_xor_sync(0xffffffffu, sm[hh], o);
    float inv[H];
#pragma unroll
    for (int hh = 0; hh < H; hh++) inv[hh] = 1.0f / (sm[hh] + 1e-16f);

    // pass 3: weighted gather-sum. lane owns channels [lane*CPL, lane*CPL+CPL)
    int c0 = lane * CPL;
    int hd = lane / G;   // head owning those channels
    float acc[CPL];
#pragma unroll
    for (int j = 0; j < CPL; j++) acc[j] = 0.f;
    float myald = aldn[hd];
    float mymx = mx[hd];
    float myinv = inv[hd];
    for (int i = s0; i < s1; i++) {
        int s = g_csr_src[i];
        float w = g_csr_w[i];
        float l = g_als[(size_t)s * H + hd] + myald;
        l = (l > 0.f) ? l : SLOPE * l;
        float alpha = __expf(l - mymx) * w * myinv;
        if (CPL == 4) {
            float4 v = *(const float4*)(g_h + (size_t)s * D + c0);
            acc[0] = fmaf(alpha, v.x, acc[0]);
            acc[1] = fmaf(alpha, v.y, acc[1]);
            acc[2] = fmaf(alpha, v.z, acc[2]);
            acc[3] = fmaf(alpha, v.w, acc[3]);
        } else {
            float2 v = *(const float2*)(g_h + (size_t)s * D + c0);
            acc[0] = fmaf(alpha, v.x, acc[0]);
            acc[1] = fmaf(alpha, v.y, acc[1]);
        }
    }
#pragma unroll
    for (int j = 0; j < CPL; j++) {
        float v = acc[j] + bias[c0 + j];
        if (RELU) v = fmaxf(v, 0.f);
        out[(size_t)node * D + c0 + j] = v;
    }
}

// ---------------- host launch ----------------
extern "C" void kernel_launch(void* const* d_in, const int* in_sizes, int n_in,
                              void* d_out, int out_size) {
    const float* x   = (const float*)d_in[0];
    const void*  ei  = d_in[1];            // int32 or int64, detected on device
    const float* ew  = (const float*)d_in[2];
    const float* W1  = (const float*)d_in[3];
    const float* aS1 = (const float*)d_in[4];
    const float* aD1 = (const float*)d_in[5];
    const float* b1  = (const float*)d_in[6];
    const float* W2  = (const float*)d_in[7];
    const float* aS2 = (const float*)d_in[8];
    const float* aD2 = (const float*)d_in[9];
    const float* b2  = (const float*)d_in[10];
    const float* W3  = (const float*)d_in[11];
    const float* aS3 = (const float*)d_in[12];
    const float* aD3 = (const float*)d_in[13];
    const float* b3  = (const float*)d_in[14];

    const int E = in_sizes[2];       // edge_weight element count == E
    const int n = NN;

    // CSR build (reused by all 3 layers)
    k_detect_idx<<<1, 32>>>(ei, E);
    k_zero_deg<<<(n + 255) / 256, 256>>>(n);
    k_count_deg<<<(E + 255) / 256, 256>>>(ei, E, n);
    k_scan_deg<<<1, 1024>>>(n);
    k_copy_cursor<<<(n + 255) / 256, 256>>>(n);
    k_scatter<<<(E + 255) / 256, 256>>>(ei, ew, E, n);

    const int nodeBlocks = (n + 3) / 4;
    dim3 gemmGrid2(128 / 64, (n + 127) / 128);   // Nc=128
    dim3 gemmGrid1(64 / 64, (n + 127) / 128);    // Nc=64

    // Layer 1: 256 -> 128, H=4, C=32, relu
    k_sgemm<<<gemmGrid2, 256>>>(x, W1, n, IN_F, D1);
    k_dots<4, 32><<<nodeBlocks, 128>>>(aS1, aD1, n);
    k_aggregate<4, 32, true><<<nodeBlocks, 128>>>(b1, nullptr, n);

    // Layer 2: 128 -> 128, H=4, C=32, relu
    k_sgemm<<<gemmGrid2, 256>>>(nullptr, W2, n, D1, D1);
    k_dots<4, 32><<<nodeBlocks, 128>>>(aS2, aD2, n);
    k_aggregate<4, 32, true><<<nodeBlocks, 128>>>(b2, nullptr, n);

    // Layer 3: 128 -> 64, H=1, C=64, no relu, mean over 1 head == identity
    k_sgemm<<<gemmGrid1, 256>>>(nullptr, W3, n, D1, OUT_F);
    k_dots<1, 64><<<nodeBlocks, 128>>>(aS3, aD3, n);
    k_aggregate<1, 64, false><<<nodeBlocks, 128>>>(b3, (float*)d_out, n);
}

// round 5
// speedup vs baseline: 1.1707x; 1.1707x over previous
#include <cuda_runtime.h>
#include <cuda_bf16.h>
#include <math.h>

// Problem constants (match reference)
#define NN 50000
#define NE 800000
#define IN_F 256
#define D1 128      // HEADS*HID
#define OUT_F 64
#define SLOPE 0.2f

#define SCAN_B 1024
#define NBLK ((NN + SCAN_B - 1) / SCAN_B)   // 49

// ---------------- device scratch (no allocations allowed) ----------------
__device__ __align__(16) float g_h[(size_t)NN * D1];     // GEMM output / layer features
__device__ __align__(16) float g_act[(size_t)NN * D1];   // post-aggregate activations
__device__ __align__(16) float g_als[(size_t)NN * 4];
__device__ __align__(16) float g_ald[(size_t)NN * 4];
__device__ int   g_rowptr[NN + 1];
__device__ int   g_deg[NN];
__device__ int   g_cursor[NN];
__device__ int   g_csr_src[NE];
__device__ float g_csr_w[NE];
__device__ int   g_bsum[NBLK];
__device__ int   g_boff[NBLK];
__device__ int   g_idx64;   // 1 if edge_index is int64, 0 if int32

// ---------------- edge-index dtype detection (parallel vote) ----------------
__global__ void k_detect_idx(const void* ei_raw, int E) {
    __shared__ int ok;
    if (threadIdx.x == 0) ok = 1;
    __syncthreads();
    const long long* p = (const long long*)ei_raw;
    int nchk = 2 * E < 256 ? 2 * E : 256;
    if (threadIdx.x < nchk) {
        long long v = p[threadIdx.x];
        if (v < 0 || v >= NN) atomicAnd(&ok, 0);
    }
    __syncthreads();
    if (threadIdx.x == 0) g_idx64 = ok;
}

__device__ __forceinline__ void load_edge(const void* ei_raw, int E, int e, int idx64,
                                          int& s, int& d) {
    if (idx64) {
        const long long* p = (const long long*)ei_raw;
        s = (int)p[e];
        d = (int)p[E + e];
    } else {
        const int* p = (const int*)ei_raw;
        s = p[e];
        d = p[E + e];
    }
}

// ---------------- CSR construction ----------------
__global__ void k_zero_deg(int n) {
    int i = blockIdx.x * blockDim.x + threadIdx.x;
    if (i < n) g_deg[i] = 0;
}

__global__ void k_count_deg(const void* ei_raw, int E, int n) {
    int e = blockIdx.x * blockDim.x + threadIdx.x;
    int idx64 = g_idx64;
    if (e < E) {
        int s, d;
        load_edge(ei_raw, E, e, idx64, s, d);
        if (d >= 0 && d < n) atomicAdd(&g_deg[d], 1);
    }
}

// -------- hierarchical scan: pass 1, per-block inclusive scan (1024 thr) --------
__global__ void k_scan1(int n) {
    int t = threadIdx.x;
    int i = blockIdx.x * SCAN_B + t;
    int lane = t & 31, w = t >> 5;
    int v = (i < n) ? g_deg[i] : 0;
    int x = v;
#pragma unroll
    for (int o = 1; o < 32; o <<= 1) {
        int y = __shfl_up_sync(0xffffffffu, x, o);
        if (lane >= o) x += y;
    }
    __shared__ int ws[32];
    if (lane == 31) ws[w] = x;
    __syncthreads();
    if (w == 0) {
        int y = ws[lane];
#pragma unroll
        for (int o = 1; o < 32; o <<= 1) {
            int z = __shfl_up_sync(0xffffffffu, y, o);
            if (lane >= o) y += z;
        }
        ws[lane] = y;
    }
    __syncthreads();
    int incl = x + (w > 0 ? ws[w - 1] : 0);
    if (i < n) g_rowptr[i + 1] = incl;      // block-local inclusive, offset added in pass 3
    if (t == SCAN_B - 1) g_bsum[blockIdx.x] = incl;
}

// -------- pass 2: exclusive scan of NBLK block sums (1 block, 64 thr) --------
__global__ void k_scan2() {
    int t = threadIdx.x;
    int lane = t & 31, w = t >> 5;
    int v = (t < NBLK) ? g_bsum[t] : 0;
    int x = v;
#pragma unroll
    for (int o = 1; o < 32; o <<= 1) {
        int y = __shfl_up_sync(0xffffffffu, x, o);
        if (lane >= o) x += y;
    }
    __shared__ int ws[2];
    if (lane == 31) ws[w] = x;
    __syncthreads();
    int incl = x + (w > 0 ? ws[0] : 0);
    if (t < NBLK) g_boff[t] = incl - v;     // exclusive
}

// -------- pass 3: add block offsets, emit rowptr + cursor --------
__global__ void k_scan3(int n) {
    int i = blockIdx.x * blockDim.x + threadIdx.x;
    if (i < n) {
        int incl = g_rowptr[i + 1] + g_boff[i >> 10];
        g_rowptr[i + 1] = incl;
        g_cursor[i] = incl - g_deg[i];       // exclusive prefix = row start
        if (i == 0) g_rowptr[0] = 0;
    }
}

__global__ void k_scatter(const void* ei_raw, const float* __restrict__ ew, int E, int n) {
    int e = blockIdx.x * blockDim.x + threadIdx.x;
    int idx64 = g_idx64;
    if (e < E) {
        int s, d;
        load_edge(ei_raw, E, e, idx64, s, d);
        if (s >= 0 && s < n && d >= 0 && d < n) {
            int pos = atomicAdd(&g_cursor[d], 1);
            if (pos >= 0 && pos < E) {
                g_csr_src[pos] = s;
                g_csr_w[pos] = ew[e];
            }
        }
    }
}

// ---------------- SGEMM: g_h[M,Nc] = A[M,K] @ B[K,Nc] ----------------
__global__ __launch_bounds__(256, 2)
void k_sgemm(const float* __restrict__ Aext, const float* __restrict__ B,
             int M, int K, int Nc) {
    constexpr int BM = 128, BN = 64, BK = 16, TM = 8, TN = 4;
    __shared__ __align__(16) float As[BK][BM];
    __shared__ __align__(16) float Bs[BK][BN];

    const float* __restrict__ A = Aext ? Aext : g_act;
    float* __restrict__ C = g_h;

    int tid = threadIdx.x;
    int tx = tid & 15;
    int ty = tid >> 4;
    int bm0 = blockIdx.y * BM;
    int bn0 = blockIdx.x * BN;

    int rA = tid >> 2;
    int kA = (tid & 3) * 4;
    int kB = tid >> 4;
    int nB = (tid & 15) * 4;

    float acc[TM][TN];
#pragma unroll
    for (int i = 0; i < TM; i++)
#pragma unroll
        for (int j = 0; j < TN; j++) acc[i][j] = 0.f;

    for (int k0 = 0; k0 < K; k0 += BK) {
#pragma unroll
        for (int it = 0; it < 2; it++) {
            int r = rA + it * 64;
            int grow = bm0 + r;
            float4 v = make_float4(0.f, 0.f, 0.f, 0.f);
            if (grow < M) v = *(const float4*)(A + (size_t)grow * K + k0 + kA);
            As[kA + 0][r] = v.x; As[kA + 1][r] = v.y;
            As[kA + 2][r] = v.z; As[kA + 3][r] = v.w;
        }
        {
            float4 v = *(const float4*)(B + (size_t)(k0 + kB) * Nc + bn0 + nB);
            *(float4*)&Bs[kB][nB] = v;
        }
        __syncthreads();
#pragma unroll
        for (int kk = 0; kk < BK; kk++) {
            float a[TM], b[TN];
#pragma unroll
            for (int i = 0; i < TM; i++) a[i] = As[kk][ty * TM + i];
#pragma unroll
            for (int j = 0; j < TN; j++) b[j] = Bs[kk][tx * TN + j];
#pragma unroll
            for (int i = 0; i < TM; i++)
#pragma unroll
                for (int j = 0; j < TN; j++) acc[i][j] = fmaf(a[i], b[j], acc[i][j]);
        }
        __syncthreads();
    }
#pragma unroll
    for (int i = 0; i < TM; i++) {
        int grow = bm0 + ty * TM + i;
        if (grow < M) {
            float4 v = make_float4(acc[i][0], acc[i][1], acc[i][2], acc[i][3]);
            *(float4*)(C + (size_t)grow * Nc + bn0 + tx * TN) = v;
        }
    }
}

// ---------------- attention dot products: g_als/g_ald [N,H] ----------------
template <int H, int C>
__global__ void k_dots(const float* __restrict__ a_src, const float* __restrict__ a_dst, int n) {
    constexpr int D = H * C;
    constexpr int CPL = D / 32;
    constexpr int G = 32 / H;
    int wid = threadIdx.x >> 5;
    int lane = threadIdx.x & 31;
    int node = blockIdx.x * 4 + wid;
    if (node >= n) return;
    int c0 = lane * CPL;
    float ss = 0.f, sd = 0.f;
    const float* hr = g_h + (size_t)node * D;
#pragma unroll
    for (int j = 0; j < CPL; j++) {
        float hv = hr[c0 + j];
        ss = fmaf(hv, a_src[c0 + j], ss);
        sd = fmaf(hv, a_dst[c0 + j], sd);
    }
#pragma unroll
    for (int o = G / 2; o > 0; o >>= 1) {
        ss += __shfl_down_sync(0xffffffffu, ss, o, G);
        sd += __shfl_down_sync(0xffffffffu, sd, o, G);
    }
    if ((lane % G) == 0) {
        int hd = lane / G;
        g_als[(size_t)node * H + hd] = ss;
        g_ald[(size_t)node * H + hd] = sd;
    }
}

// ---------------- fused segment softmax + weighted aggregate ----------------
template <int H, int C, bool RELU>
__global__ void k_aggregate(const float* __restrict__ bias, float* __restrict__ outExt, int n) {
    constexpr int D = H * C;
    constexpr int CPL = D / 32;
    constexpr int G = 32 / H;
    float* __restrict__ out = outExt ? outExt : g_act;
    int wid = threadIdx.x >> 5;
    int lane = threadIdx.x & 31;
    int node = blockIdx.x * 4 + wid;
    if (node >= n) return;

    int s0 = g_rowptr[node];
    int s1 = g_rowptr[node + 1];

    float aldn[H];
#pragma unroll
    for (int hh = 0; hh < H; hh++) aldn[hh] = g_ald[(size_t)node * H + hh];

    float mx[H];
#pragma unroll
    for (int hh = 0; hh < H; hh++) mx[hh] = -1e30f;
    for (int i = s0 + lane; i < s1; i += 32) {
        int s = g_csr_src[i];
#pragma unroll
        for (int hh = 0; hh < H; hh++) {
            float l = g_als[(size_t)s * H + hh] + aldn[hh];
            l = (l > 0.f) ? l : SLOPE * l;
            mx[hh] = fmaxf(mx[hh], l);
        }
    }
#pragma unroll
    for (int hh = 0; hh < H; hh++)
#pragma unroll
        for (int o = 16; o > 0; o >>= 1)
            mx[hh] = fmaxf(mx[hh], __shfl_xor_sync(0xffffffffu, mx[hh], o));

    float sm[H];
#pragma unroll
    for (int hh = 0; hh < H; hh++) sm[hh] = 0.f;
    for (int i = s0 + lane; i < s1; i += 32) {
        int s = g_csr_src[i];
        float w = g_csr_w[i];
#pragma unroll
        for (int hh = 0; hh < H; hh++) {
            float l = g_als[(size_t)s * H + hh] + aldn[hh];
            l = (l > 0.f) ? l : SLOPE * l;
            sm[hh] += __expf(l - mx[hh]) * w;
        }
    }
#pragma unroll
    for (int hh = 0; hh < H; hh++)
#pragma unroll
        for (int o = 16; o > 0; o >>= 1)
            sm[hh] += __shfl_xor_sync(0xffffffffu, sm[hh], o);
    float inv[H];
#pragma unroll
    for (int hh = 0; hh < H; hh++) inv[hh] = 1.0f / (sm[hh] + 1e-16f);

    int c0 = lane * CPL;
    int hd = lane / G;
    float acc[CPL];
#pragma unroll
    for (int j = 0; j < CPL; j++) acc[j] = 0.f;
    float myald = aldn[hd];
    float mymx = mx[hd];
    float myinv = inv[hd];
    for (int i = s0; i < s1; i++) {
        int s = g_csr_src[i];
        float w = g_csr_w[i];
        float l = g_als[(size_t)s * H + hd] + myald;
        l = (l > 0.f) ? l : SLOPE * l;
        float alpha = __expf(l - mymx) * w * myinv;
        if (CPL == 4) {
            float4 v = *(const float4*)(g_h + (size_t)s * D + c0);
            acc[0] = fmaf(alpha, v.x, acc[0]);
            acc[1] = fmaf(alpha, v.y, acc[1]);
            acc[2] = fmaf(alpha, v.z, acc[2]);
            acc[3] = fmaf(alpha, v.w, acc[3]);
        } else {
            float2 v = *(const float2*)(g_h + (size_t)s * D + c0);
            acc[0] = fmaf(alpha, v.x, acc[0]);
            acc[1] = fmaf(alpha, v.y, acc[1]);
        }
    }
#pragma unroll
    for (int j = 0; j < CPL; j++) {
        float v = acc[j] + bias[c0 + j];
        if (RELU) v = fmaxf(v, 0.f);
        out[(size_t)node * D + c0 + j] = v;
    }
}

// ---------------- host launch ----------------
extern "C" void kernel_launch(void* const* d_in, const int* in_sizes, int n_in,
                              void* d_out, int out_size) {
    const float* x   = (const float*)d_in[0];
    const void*  ei  = d_in[1];            // int32 or int64, detected on device
    const float* ew  = (const float*)d_in[2];
    const float* W1  = (const float*)d_in[3];
    const float* aS1 = (const float*)d_in[4];
    const float* aD1 = (const float*)d_in[5];
    const float* b1  = (const float*)d_in[6];
    const float* W2  = (const float*)d_in[7];
    const float* aS2 = (const float*)d_in[8];
    const float* aD2 = (const float*)d_in[9];
    const float* b2  = (const float*)d_in[10];
    const float* W3  = (const float*)d_in[11];
    const float* aS3 = (const float*)d_in[12];
    const float* aD3 = (const float*)d_in[13];
    const float* b3  = (const float*)d_in[14];

    const int E = in_sizes[2];       // edge_weight element count == E
    const int n = NN;

    // CSR build (reused by all 3 layers)
    k_detect_idx<<<1, 256>>>(ei, E);
    k_zero_deg<<<(n + 255) / 256, 256>>>(n);
    k_count_deg<<<(E + 255) / 256, 256>>>(ei, E, n);
    k_scan1<<<NBLK, SCAN_B>>>(n);
    k_scan2<<<1, 64>>>();
    k_scan3<<<(n + 255) / 256, 256>>>(n);
    k_scatter<<<(E + 255) / 256, 256>>>(ei, ew, E, n);

    const int nodeBlocks = (n + 3) / 4;
    dim3 gemmGrid2(128 / 64, (n + 127) / 128);   // Nc=128
    dim3 gemmGrid1(64 / 64, (n + 127) / 128);    // Nc=64

    // Layer 1: 256 -> 128, H=4, C=32, relu
    k_sgemm<<<gemmGrid2, 256>>>(x, W1, n, IN_F, D1);
    k_dots<4, 32><<<nodeBlocks, 128>>>(aS1, aD1, n);
    k_aggregate<4, 32, true><<<nodeBlocks, 128>>>(b1, nullptr, n);

    // Layer 2: 128 -> 128, H=4, C=32, relu
    k_sgemm<<<gemmGrid2, 256>>>(nullptr, W2, n, D1, D1);
    k_dots<4, 32><<<nodeBlocks, 128>>>(aS2, aD2, n);
    k_aggregate<4, 32, true><<<nodeBlocks, 128>>>(b2, nullptr, n);

    // Layer 3: 128 -> 64, H=1, C=64, no relu
    k_sgemm<<<gemmGrid1, 256>>>(nullptr, W3, n, D1, OUT_F);
    k_dots<1, 64><<<nodeBlocks, 128>>>(aS3, aD3, n);
    k_aggregate<1, 64, false><<<nodeBlocks, 128>>>(b3, (float*)d_out, n);
}

// round 6
// speedup vs baseline: 1.6444x; 1.4047x over previous
#include <cuda_runtime.h>
#include <cuda_bf16.h>
#include <math.h>

// Problem constants (match reference)
#define NN 50000
#define NE 800000
#define IN_F 256
#define D1 128      // HEADS*HID
#define OUT_F 64
#define SLOPE 0.2f

#define SCAN_B 1024
#define NBLK ((NN + SCAN_B - 1) / SCAN_B)   // 49

// ---------------- device scratch (no allocations allowed) ----------------
__device__ __align__(16) float g_h[(size_t)NN * D1];     // GEMM output / layer features
__device__ __align__(16) float g_act[(size_t)NN * D1];   // post-aggregate activations
__device__ __align__(16) float g_als[(size_t)NN * 4];
__device__ __align__(16) float g_ald[(size_t)NN * 4];
__device__ int   g_rowptr[NN + 1];
__device__ int   g_deg[NN];
__device__ int   g_cursor[NN];
__device__ int   g_csr_src[NE];
__device__ float g_csr_w[NE];
__device__ int   g_bsum[NBLK];
__device__ int   g_boff[NBLK];
__device__ int   g_idx64;   // 1 if edge_index is int64, 0 if int32

// ---------------- edge-index dtype detection (parallel vote) ----------------
__global__ void k_detect_idx(const void* ei_raw, int E) {
    __shared__ int ok;
    if (threadIdx.x == 0) ok = 1;
    __syncthreads();
    const long long* p = (const long long*)ei_raw;
    int nchk = 2 * E < 256 ? 2 * E : 256;
    if (threadIdx.x < nchk) {
        long long v = p[threadIdx.x];
        if (v < 0 || v >= NN) atomicAnd(&ok, 0);
    }
    __syncthreads();
    if (threadIdx.x == 0) g_idx64 = ok;
}

__device__ __forceinline__ void load_edge(const void* ei_raw, int E, int e, int idx64,
                                          int& s, int& d) {
    if (idx64) {
        const long long* p = (const long long*)ei_raw;
        s = (int)p[e];
        d = (int)p[E + e];
    } else {
        const int* p = (const int*)ei_raw;
        s = p[e];
        d = p[E + e];
    }
}

// ---------------- CSR construction ----------------
__global__ void k_zero_deg(int n) {
    int i = blockIdx.x * blockDim.x + threadIdx.x;
    if (i < n) g_deg[i] = 0;
}

__global__ void k_count_deg(const void* ei_raw, int E, int n) {
    int e = blockIdx.x * blockDim.x + threadIdx.x;
    int idx64 = g_idx64;
    if (e < E) {
        int s, d;
        load_edge(ei_raw, E, e, idx64, s, d);
        if (d >= 0 && d < n) atomicAdd(&g_deg[d], 1);
    }
}

__global__ void k_scan1(int n) {
    int t = threadIdx.x;
    int i = blockIdx.x * SCAN_B + t;
    int lane = t & 31, w = t >> 5;
    int v = (i < n) ? g_deg[i] : 0;
    int x = v;
#pragma unroll
    for (int o = 1; o < 32; o <<= 1) {
        int y = __shfl_up_sync(0xffffffffu, x, o);
        if (lane >= o) x += y;
    }
    __shared__ int ws[32];
    if (lane == 31) ws[w] = x;
    __syncthreads();
    if (w == 0) {
        int y = ws[lane];
#pragma unroll
        for (int o = 1; o < 32; o <<= 1) {
            int z = __shfl_up_sync(0xffffffffu, y, o);
            if (lane >= o) y += z;
        }
        ws[lane] = y;
    }
    __syncthreads();
    int incl = x + (w > 0 ? ws[w - 1] : 0);
    if (i < n) g_rowptr[i + 1] = incl;
    if (t == SCAN_B - 1) g_bsum[blockIdx.x] = incl;
}

__global__ void k_scan2() {
    int t = threadIdx.x;
    int lane = t & 31, w = t >> 5;
    int v = (t < NBLK) ? g_bsum[t] : 0;
    int x = v;
#pragma unroll
    for (int o = 1; o < 32; o <<= 1) {
        int y = __shfl_up_sync(0xffffffffu, x, o);
        if (lane >= o) x += y;
    }
    __shared__ int ws[2];
    if (lane == 31) ws[w] = x;
    __syncthreads();
    int incl = x + (w > 0 ? ws[0] : 0);
    if (t < NBLK) g_boff[t] = incl - v;
}

__global__ void k_scan3(int n) {
    int i = blockIdx.x * blockDim.x + threadIdx.x;
    if (i < n) {
        int incl = g_rowptr[i + 1] + g_boff[i >> 10];
        g_rowptr[i + 1] = incl;
        g_cursor[i] = incl - g_deg[i];
        if (i == 0) g_rowptr[0] = 0;
    }
}

__global__ void k_scatter(const void* ei_raw, const float* __restrict__ ew, int E, int n) {
    int e = blockIdx.x * blockDim.x + threadIdx.x;
    int idx64 = g_idx64;
    if (e < E) {
        int s, d;
        load_edge(ei_raw, E, e, idx64, s, d);
        if (s >= 0 && s < n && d >= 0 && d < n) {
            int pos = atomicAdd(&g_cursor[d], 1);
            if (pos >= 0 && pos < E) {
                g_csr_src[pos] = s;
                g_csr_w[pos] = ew[e];
            }
        }
    }
}

// ---------------- TF32 tensor-core GEMM: g_h[M,Nc] = A[M,K] @ B[K,Nc] ----------------
// BM=128, BN=64, BK=32, 256 threads = 8 warps (4x2), warp tile 32x32,
// mma.m16n8k8 tf32. A = Aext if non-null else g_act.
__device__ __forceinline__ unsigned f2tf(float f) {
    unsigned u;
    asm("cvt.rna.tf32.f32 %0, %1;" : "=r"(u) : "f"(f));
    return u;
}

__global__ __launch_bounds__(256)
void k_gemm_tf32(const float* __restrict__ Aext, const float* __restrict__ B,
                 int M, int K, int Nc) {
    constexpr int BM = 128, BN = 64, BK = 32;
    constexpr int APAD = 36;   // row pitch of As (conflict-free frag reads)
    constexpr int BPAD = 72;   // row pitch of Bs
    __shared__ __align__(16) unsigned As[BM][APAD];   // [m][k] tf32 bits
    __shared__ __align__(16) unsigned Bs[BK][BPAD];   // [k][n] tf32 bits

    const float* __restrict__ A = Aext ? Aext : g_act;
    float* __restrict__ C = g_h;

    int tid = threadIdx.x;
    int lane = tid & 31;
    int warp = tid >> 5;
    int wm = warp >> 1;          // 0..3 -> m offset wm*32
    int wn = warp & 1;           // 0..1 -> n offset wn*32
    int bm0 = blockIdx.y * BM;
    int bn0 = blockIdx.x * BN;

    float acc[2][4][4];
#pragma unroll
    for (int mt = 0; mt < 2; mt++)
#pragma unroll
        for (int nt = 0; nt < 4; nt++)
#pragma unroll
            for (int i = 0; i < 4; i++) acc[mt][nt][i] = 0.f;

    // A-tile loader mapping: 2 threads per row, 4 float4 each
    int arow = tid >> 1;                  // 0..127
    int acol0 = (tid & 1) * 16;           // 0 or 16
    // B-tile loader mapping: 8 threads per row, 2 float4 each
    int brow = tid >> 3;                  // 0..31
    int bcol0 = (tid & 7) * 4;            // 0..28

    for (int k0 = 0; k0 < K; k0 += BK) {
        // load A tile (guarded on M)
        int grow = bm0 + arow;
        const float* ap = A + (size_t)grow * K + k0 + acol0;
#pragma unroll
        for (int j = 0; j < 4; j++) {
            float4 v = make_float4(0.f, 0.f, 0.f, 0.f);
            if (grow < M) v = *(const float4*)(ap + j * 4);
            unsigned* dstp = &As[arow][acol0 + j * 4];
            dstp[0] = f2tf(v.x); dstp[1] = f2tf(v.y);
            dstp[2] = f2tf(v.z); dstp[3] = f2tf(v.w);
        }
        // load B tile (K,Nc multiples of tile => unguarded)
        const float* bp = B + (size_t)(k0 + brow) * Nc + bn0;
#pragma unroll
        for (int it = 0; it < 2; it++) {
            int c = bcol0 + it * 32;
            float4 v = *(const float4*)(bp + c);
            unsigned* dstp = &Bs[brow][c];
            dstp[0] = f2tf(v.x); dstp[1] = f2tf(v.y);
            dstp[2] = f2tf(v.z); dstp[3] = f2tf(v.w);
        }
        __syncthreads();

#pragma unroll
        for (int kc = 0; kc < BK; kc += 8) {
            unsigned afr[2][4];
            int r0 = wm * 32 + (lane >> 2);
            int cA = kc + (lane & 3);
#pragma unroll
            for (int mt = 0; mt < 2; mt++) {
                int rb = r0 + mt * 16;
                afr[mt][0] = As[rb][cA];
                afr[mt][1] = As[rb + 8][cA];
                afr[mt][2] = As[rb][cA + 4];
                afr[mt][3] = As[rb + 8][cA + 4];
            }
            unsigned bfr[4][2];
            int kB0 = kc + (lane & 3);
            int nB0 = wn * 32 + (lane >> 2);
#pragma unroll
            for (int nt = 0; nt < 4; nt++) {
                bfr[nt][0] = Bs[kB0][nB0 + nt * 8];
                bfr[nt][1] = Bs[kB0 + 4][nB0 + nt * 8];
            }
#pragma unroll
            for (int mt = 0; mt < 2; mt++)
#pragma unroll
                for (int nt = 0; nt < 4; nt++) {
                    asm volatile(
                        "mma.sync.aligned.m16n8k8.row.col.f32.tf32.tf32.f32 "
                        "{%0,%1,%2,%3}, {%4,%5,%6,%7}, {%8,%9}, {%0,%1,%2,%3};"
                        : "+f"(acc[mt][nt][0]), "+f"(acc[mt][nt][1]),
                          "+f"(acc[mt][nt][2]), "+f"(acc[mt][nt][3])
                        : "r"(afr[mt][0]), "r"(afr[mt][1]), "r"(afr[mt][2]), "r"(afr[mt][3]),
                          "r"(bfr[nt][0]), "r"(bfr[nt][1]));
                }
        }
        __syncthreads();
    }

    // epilogue
#pragma unroll
    for (int mt = 0; mt < 2; mt++) {
        int r = bm0 + wm * 32 + mt * 16 + (lane >> 2);
#pragma unroll
        for (int nt = 0; nt < 4; nt++) {
            int c = bn0 + wn * 32 + nt * 8 + (lane & 3) * 2;
            if (r < M) {
                float2 v0 = make_float2(acc[mt][nt][0], acc[mt][nt][1]);
                *(float2*)(C + (size_t)r * Nc + c) = v0;
            }
            if (r + 8 < M) {
                float2 v1 = make_float2(acc[mt][nt][2], acc[mt][nt][3]);
                *(float2*)(C + (size_t)(r + 8) * Nc + c) = v1;
            }
        }
    }
}

// ---------------- attention dot products: g_als/g_ald [N,H] ----------------
template <int H, int C>
__global__ void k_dots(const float* __restrict__ a_src, const float* __restrict__ a_dst, int n) {
    constexpr int D = H * C;
    constexpr int CPL = D / 32;
    constexpr int G = 32 / H;
    int wid = threadIdx.x >> 5;
    int lane = threadIdx.x & 31;
    int node = blockIdx.x * 4 + wid;
    if (node >= n) return;
    int c0 = lane * CPL;
    float ss = 0.f, sd = 0.f;
    const float* hr = g_h + (size_t)node * D;
#pragma unroll
    for (int j = 0; j < CPL; j++) {
        float hv = hr[c0 + j];
        ss = fmaf(hv, a_src[c0 + j], ss);
        sd = fmaf(hv, a_dst[c0 + j], sd);
    }
#pragma unroll
    for (int o = G / 2; o > 0; o >>= 1) {
        ss += __shfl_down_sync(0xffffffffu, ss, o, G);
        sd += __shfl_down_sync(0xffffffffu, sd, o, G);
    }
    if ((lane % G) == 0) {
        int hd = lane / G;
        g_als[(size_t)node * H + hd] = ss;
        g_ald[(size_t)node * H + hd] = sd;
    }
}

// ---------------- fused segment softmax + weighted aggregate ----------------
// pass1: per-head max; pass2 (fused): accumulate numerator & denominator together.
template <int H, int C, bool RELU>
__global__ void k_aggregate(const float* __restrict__ bias, float* __restrict__ outExt, int n) {
    constexpr int D = H * C;
    constexpr int CPL = D / 32;
    constexpr int G = 32 / H;
    float* __restrict__ out = outExt ? outExt : g_act;
    int wid = threadIdx.x >> 5;
    int lane = threadIdx.x & 31;
    int node = blockIdx.x * 4 + wid;
    if (node >= n) return;

    int s0 = g_rowptr[node];
    int s1 = g_rowptr[node + 1];

    float aldn[H];
#pragma unroll
    for (int hh = 0; hh < H; hh++) aldn[hh] = g_ald[(size_t)node * H + hh];

    // pass 1: per-head max of leaky logits (lanes stride edges)
    float mx[H];
#pragma unroll
    for (int hh = 0; hh < H; hh++) mx[hh] = -1e30f;
    for (int i = s0 + lane; i < s1; i += 32) {
        int s = g_csr_src[i];
#pragma unroll
        for (int hh = 0; hh < H; hh++) {
            float l = g_als[(size_t)s * H + hh] + aldn[hh];
            l = (l > 0.f) ? l : SLOPE * l;
            mx[hh] = fmaxf(mx[hh], l);
        }
    }
#pragma unroll
    for (int hh = 0; hh < H; hh++)
#pragma unroll
        for (int o = 16; o > 0; o >>= 1)
            mx[hh] = fmaxf(mx[hh], __shfl_xor_sync(0xffffffffu, mx[hh], o));

    // pass 2 (fused): serial over edges, lanes own channels; accumulate num + denom
    int c0 = lane * CPL;
    int hd = lane / G;
    float acc[CPL];
#pragma unroll
    for (int j = 0; j < CPL; j++) acc[j] = 0.f;
    float esum = 0.f;
    float myald = aldn[hd];
    float mymx = mx[hd];
    for (int i = s0; i < s1; i++) {
        int s = g_csr_src[i];
        float w = g_csr_w[i];
        float l = g_als[(size_t)s * H + hd] + myald;
        l = (l > 0.f) ? l : SLOPE * l;
        float e = __expf(l - mymx) * w;
        esum += e;
        if (CPL == 4) {
            float4 v = *(const float4*)(g_h + (size_t)s * D + c0);
            acc[0] = fmaf(e, v.x, acc[0]);
            acc[1] = fmaf(e, v.y, acc[1]);
            acc[2] = fmaf(e, v.z, acc[2]);
            acc[3] = fmaf(e, v.w, acc[3]);
        } else {
            float2 v = *(const float2*)(g_h + (size_t)s * D + c0);
            acc[0] = fmaf(e, v.x, acc[0]);
            acc[1] = fmaf(e, v.y, acc[1]);
        }
    }
    float inv = 1.0f / (esum + 1e-16f);
#pragma unroll
    for (int j = 0; j < CPL; j++) {
        float v = fmaf(acc[j], inv, bias[c0 + j]);
        if (RELU) v = fmaxf(v, 0.f);
        out[(size_t)node * D + c0 + j] = v;
    }
}

// ---------------- host launch ----------------
extern "C" void kernel_launch(void* const* d_in, const int* in_sizes, int n_in,
                              void* d_out, int out_size) {
    const float* x   = (const float*)d_in[0];
    const void*  ei  = d_in[1];            // int32 or int64, detected on device
    const float* ew  = (const float*)d_in[2];
    const float* W1  = (const float*)d_in[3];
    const float* aS1 = (const float*)d_in[4];
    const float* aD1 = (const float*)d_in[5];
    const float* b1  = (const float*)d_in[6];
    const float* W2  = (const float*)d_in[7];
    const float* aS2 = (const float*)d_in[8];
    const float* aD2 = (const float*)d_in[9];
    const float* b2  = (const float*)d_in[10];
    const float* W3  = (const float*)d_in[11];
    const float* aS3 = (const float*)d_in[12];
    const float* aD3 = (const float*)d_in[13];
    const float* b3  = (const float*)d_in[14];

    const int E = in_sizes[2];       // edge_weight element count == E
    const int n = NN;

    // CSR build (reused by all 3 layers)
    k_detect_idx<<<1, 256>>>(ei, E);
    k_zero_deg<<<(n + 255) / 256, 256>>>(n);
    k_count_deg<<<(E + 255) / 256, 256>>>(ei, E, n);
    k_scan1<<<NBLK, SCAN_B>>>(n);
    k_scan2<<<1, 64>>>();
    k_scan3<<<(n + 255) / 256, 256>>>(n);
    k_scatter<<<(E + 255) / 256, 256>>>(ei, ew, E, n);

    const int nodeBlocks = (n + 3) / 4;
    dim3 gemmGrid2(D1 / 64, (n + 127) / 128);    // Nc=128 -> x=2
    dim3 gemmGrid1(OUT_F / 64, (n + 127) / 128); // Nc=64  -> x=1

    // Layer 1: 256 -> 128, H=4, C=32, relu
    k_gemm_tf32<<<gemmGrid2, 256>>>(x, W1, n, IN_F, D1);
    k_dots<4, 32><<<nodeBlocks, 128>>>(aS1, aD1, n);
    k_aggregate<4, 32, true><<<nodeBlocks, 128>>>(b1, nullptr, n);

    // Layer 2: 128 -> 128, H=4, C=32, relu
    k_gemm_tf32<<<gemmGrid2, 256>>>(nullptr, W2, n, D1, D1);
    k_dots<4, 32><<<nodeBlocks, 128>>>(aS2, aD2, n);
    k_aggregate<4, 32, true><<<nodeBlocks, 128>>>(b2, nullptr, n);

    // Layer 3: 128 -> 64, H=1, C=64, no relu
    k_gemm_tf32<<<gemmGrid1, 256>>>(nullptr, W3, n, D1, OUT_F);
    k_dots<1, 64><<<nodeBlocks, 128>>>(aS3, aD3, n);
    k_aggregate<1, 64, false><<<nodeBlocks, 128>>>(b3, (float*)d_out, n);
}

// round 7
// speedup vs baseline: 1.7411x; 1.0588x over previous
#include <cuda_runtime.h>
#include <cuda_bf16.h>
#include <math.h>

// Problem constants (match reference)
#define NN 50000
#define NE 800000
#define IN_F 256
#define D1 128      // HEADS*HID
#define OUT_F 64
#define SLOPE 0.2f

#define SCAN_B 1024
#define NBLK ((NN + SCAN_B - 1) / SCAN_B)   // 49

// ---------------- device scratch (no allocations allowed) ----------------
__device__ __align__(16) float g_h[(size_t)NN * D1];     // GEMM output / layer features
__device__ __align__(16) float g_act[(size_t)NN * D1];   // post-aggregate activations
__device__ __align__(16) float g_als[(size_t)NN * 4];
__device__ __align__(16) float g_ald[(size_t)NN * 4];
__device__ int   g_rowptr[NN + 1];
__device__ int   g_deg[NN];
__device__ int   g_cursor[NN];
__device__ __align__(8) int2 g_csr[NE];    // (src, weight-bits) packed
__device__ int   g_bsum[NBLK];
__device__ int   g_boff[NBLK];
__device__ unsigned g_mxals[3][4];         // per-layer per-head global max(als), int-encoded
__device__ int   g_idx64;   // 1 if edge_index is int64, 0 if int32

// monotone float<->uint encoding for atomicMax on floats
__device__ __forceinline__ unsigned fenc(float f) {
    int b = __float_as_int(f);
    return (b >= 0) ? ((unsigned)b | 0x80000000u) : ~(unsigned)b;
}
__device__ __forceinline__ float fdec(unsigned u) {
    int b = (u & 0x80000000u) ? (int)(u & 0x7fffffffu) : ~(int)u;
    return __int_as_float(b);
}

// ---------------- edge-index dtype detection (parallel vote) ----------------
__global__ void k_detect_idx(const void* ei_raw, int E) {
    __shared__ int ok;
    if (threadIdx.x == 0) ok = 1;
    __syncthreads();
    const long long* p = (const long long*)ei_raw;
    int nchk = 2 * E < 256 ? 2 * E : 256;
    if (threadIdx.x < nchk) {
        long long v = p[threadIdx.x];
        if (v < 0 || v >= NN) atomicAnd(&ok, 0);
    }
    __syncthreads();
    if (threadIdx.x == 0) g_idx64 = ok;
}

__device__ __forceinline__ void load_edge(const void* ei_raw, int E, int e, int idx64,
                                          int& s, int& d) {
    if (idx64) {
        const long long* p = (const long long*)ei_raw;
        s = (int)p[e];
        d = (int)p[E + e];
    } else {
        const int* p = (const int*)ei_raw;
        s = p[e];
        d = p[E + e];
    }
}

// ---------------- CSR construction ----------------
__global__ void k_zero_deg(int n) {
    int i = blockIdx.x * blockDim.x + threadIdx.x;
    if (i < n) g_deg[i] = 0;
}

__global__ void k_count_deg(const void* ei_raw, int E, int n) {
    int e = blockIdx.x * blockDim.x + threadIdx.x;
    int idx64 = g_idx64;
    if (e < E) {
        int s, d;
        load_edge(ei_raw, E, e, idx64, s, d);
        if (d >= 0 && d < n) atomicAdd(&g_deg[d], 1);
    }
}

__global__ void k_scan1(int n) {
    int t = threadIdx.x;
    int i = blockIdx.x * SCAN_B + t;
    int lane = t & 31, w = t >> 5;
    int v = (i < n) ? g_deg[i] : 0;
    int x = v;
#pragma unroll
    for (int o = 1; o < 32; o <<= 1) {
        int y = __shfl_up_sync(0xffffffffu, x, o);
        if (lane >= o) x += y;
    }
    __shared__ int ws[32];
    if (lane == 31) ws[w] = x;
    __syncthreads();
    if (w == 0) {
        int y = ws[lane];
#pragma unroll
        for (int o = 1; o < 32; o <<= 1) {
            int z = __shfl_up_sync(0xffffffffu, y, o);
            if (lane >= o) y += z;
        }
        ws[lane] = y;
    }
    __syncthreads();
    int incl = x + (w > 0 ? ws[w - 1] : 0);
    if (i < n) g_rowptr[i + 1] = incl;
    if (t == SCAN_B - 1) g_bsum[blockIdx.x] = incl;
}

__global__ void k_scan2() {
    int t = threadIdx.x;
    int lane = t & 31, w = t >> 5;
    if (t < 12) ((unsigned*)g_mxals)[t] = 0u;    // init per-layer max slots
    int v = (t < NBLK) ? g_bsum[t] : 0;
    int x = v;
#pragma unroll
    for (int o = 1; o < 32; o <<= 1) {
        int y = __shfl_up_sync(0xffffffffu, x, o);
        if (lane >= o) x += y;
    }
    __shared__ int ws[2];
    if (lane == 31) ws[w] = x;
    __syncthreads();
    int incl = x + (w > 0 ? ws[0] : 0);
    if (t < NBLK) g_boff[t] = incl - v;
}

__global__ void k_scan3(int n) {
    int i = blockIdx.x * blockDim.x + threadIdx.x;
    if (i < n) {
        int incl = g_rowptr[i + 1] + g_boff[i >> 10];
        g_rowptr[i + 1] = incl;
        g_cursor[i] = incl - g_deg[i];
        if (i == 0) g_rowptr[0] = 0;
    }
}

__global__ void k_scatter(const void* ei_raw, const float* __restrict__ ew, int E, int n) {
    int e = blockIdx.x * blockDim.x + threadIdx.x;
    int idx64 = g_idx64;
    if (e < E) {
        int s, d;
        load_edge(ei_raw, E, e, idx64, s, d);
        if (s >= 0 && s < n && d >= 0 && d < n) {
            int pos = atomicAdd(&g_cursor[d], 1);
            if (pos >= 0 && pos < E) {
                g_csr[pos] = make_int2(s, __float_as_int(ew[e]));
            }
        }
    }
}

// ---------------- TF32 tensor-core GEMM: g_h[M,Nc] = A[M,K] @ B[K,Nc] ----------------
__device__ __forceinline__ unsigned f2tf(float f) {
    unsigned u;
    asm("cvt.rna.tf32.f32 %0, %1;" : "=r"(u) : "f"(f));
    return u;
}

__global__ __launch_bounds__(256)
void k_gemm_tf32(const float* __restrict__ Aext, const float* __restrict__ B,
                 int M, int K, int Nc) {
    constexpr int BM = 128, BN = 64, BK = 32;
    constexpr int APAD = 36;
    constexpr int BPAD = 72;
    __shared__ __align__(16) unsigned As[BM][APAD];
    __shared__ __align__(16) unsigned Bs[BK][BPAD];

    const float* __restrict__ A = Aext ? Aext : g_act;
    float* __restrict__ C = g_h;

    int tid = threadIdx.x;
    int lane = tid & 31;
    int warp = tid >> 5;
    int wm = warp >> 1;
    int wn = warp & 1;
    int bm0 = blockIdx.y * BM;
    int bn0 = blockIdx.x * BN;

    float acc[2][4][4];
#pragma unroll
    for (int mt = 0; mt < 2; mt++)
#pragma unroll
        for (int nt = 0; nt < 4; nt++)
#pragma unroll
            for (int i = 0; i < 4; i++) acc[mt][nt][i] = 0.f;

    int arow = tid >> 1;
    int acol0 = (tid & 1) * 16;
    int brow = tid >> 3;
    int bcol0 = (tid & 7) * 4;

    for (int k0 = 0; k0 < K; k0 += BK) {
        int grow = bm0 + arow;
        const float* ap = A + (size_t)grow * K + k0 + acol0;
#pragma unroll
        for (int j = 0; j < 4; j++) {
            float4 v = make_float4(0.f, 0.f, 0.f, 0.f);
            if (grow < M) v = *(const float4*)(ap + j * 4);
            unsigned* dstp = &As[arow][acol0 + j * 4];
            dstp[0] = f2tf(v.x); dstp[1] = f2tf(v.y);
            dstp[2] = f2tf(v.z); dstp[3] = f2tf(v.w);
        }
        const float* bp = B + (size_t)(k0 + brow) * Nc + bn0;
#pragma unroll
        for (int it = 0; it < 2; it++) {
            int c = bcol0 + it * 32;
            float4 v = *(const float4*)(bp + c);
            unsigned* dstp = &Bs[brow][c];
            dstp[0] = f2tf(v.x); dstp[1] = f2tf(v.y);
            dstp[2] = f2tf(v.z); dstp[3] = f2tf(v.w);
        }
        __syncthreads();

#pragma unroll
        for (int kc = 0; kc < BK; kc += 8) {
            unsigned afr[2][4];
            int r0 = wm * 32 + (lane >> 2);
            int cA = kc + (lane & 3);
#pragma unroll
            for (int mt = 0; mt < 2; mt++) {
                int rb = r0 + mt * 16;
                afr[mt][0] = As[rb][cA];
                afr[mt][1] = As[rb + 8][cA];
                afr[mt][2] = As[rb][cA + 4];
                afr[mt][3] = As[rb + 8][cA + 4];
            }
            unsigned bfr[4][2];
            int kB0 = kc + (lane & 3);
            int nB0 = wn * 32 + (lane >> 2);
#pragma unroll
            for (int nt = 0; nt < 4; nt++) {
                bfr[nt][0] = Bs[kB0][nB0 + nt * 8];
                bfr[nt][1] = Bs[kB0 + 4][nB0 + nt * 8];
            }
#pragma unroll
            for (int mt = 0; mt < 2; mt++)
#pragma unroll
                for (int nt = 0; nt < 4; nt++) {
                    asm volatile(
                        "mma.sync.aligned.m16n8k8.row.col.f32.tf32.tf32.f32 "
                        "{%0,%1,%2,%3}, {%4,%5,%6,%7}, {%8,%9}, {%0,%1,%2,%3};"
                        : "+f"(acc[mt][nt][0]), "+f"(acc[mt][nt][1]),
                          "+f"(acc[mt][nt][2]), "+f"(acc[mt][nt][3])
                        : "r"(afr[mt][0]), "r"(afr[mt][1]), "r"(afr[mt][2]), "r"(afr[mt][3]),
                          "r"(bfr[nt][0]), "r"(bfr[nt][1]));
                }
        }
        __syncthreads();
    }

#pragma unroll
    for (int mt = 0; mt < 2; mt++) {
        int r = bm0 + wm * 32 + mt * 16 + (lane >> 2);
#pragma unroll
        for (int nt = 0; nt < 4; nt++) {
            int c = bn0 + wn * 32 + nt * 8 + (lane & 3) * 2;
            if (r < M) {
                float2 v0 = make_float2(acc[mt][nt][0], acc[mt][nt][1]);
                *(float2*)(C + (size_t)r * Nc + c) = v0;
            }
            if (r + 8 < M) {
                float2 v1 = make_float2(acc[mt][nt][2], acc[mt][nt][3]);
                *(float2*)(C + (size_t)(r + 8) * Nc + c) = v1;
            }
        }
    }
}

// ---------------- attention dot products: g_als/g_ald [N,H] ----------------
template <int H, int C>
__global__ void k_dots(const float* __restrict__ a_src, const float* __restrict__ a_dst, int n) {
    constexpr int D = H * C;
    constexpr int CPL = D / 32;
    constexpr int G = 32 / H;
    int wid = threadIdx.x >> 5;
    int lane = threadIdx.x & 31;
    int node = blockIdx.x * 4 + wid;
    if (node >= n) return;
    int c0 = lane * CPL;
    float ss = 0.f, sd = 0.f;
    const float* hr = g_h + (size_t)node * D;
#pragma unroll
    for (int j = 0; j < CPL; j++) {
        float hv = hr[c0 + j];
        ss = fmaf(hv, a_src[c0 + j], ss);
        sd = fmaf(hv, a_dst[c0 + j], sd);
    }
#pragma unroll
    for (int o = G / 2; o > 0; o >>= 1) {
        ss += __shfl_down_sync(0xffffffffu, ss, o, G);
        sd += __shfl_down_sync(0xffffffffu, sd, o, G);
    }
    if ((lane % G) == 0) {
        int hd = lane / G;
        g_als[(size_t)node * H + hd] = ss;
        g_ald[(size_t)node * H + hd] = sd;
    }
}

// ---------------- global per-head max of als (upper bound for softmax shift) ----------------
template <int H, int LAYER>
__global__ void k_maxals(int n) {
    float mx[H];
#pragma unroll
    for (int hh = 0; hh < H; hh++) mx[hh] = -1e30f;
    for (int i = blockIdx.x * blockDim.x + threadIdx.x; i < n; i += gridDim.x * blockDim.x) {
        if (H == 4) {
            float4 v = *(const float4*)(g_als + (size_t)i * 4);
            mx[0] = fmaxf(mx[0], v.x); mx[1] = fmaxf(mx[1], v.y);
            mx[2] = fmaxf(mx[2], v.z); mx[3] = fmaxf(mx[3], v.w);
        } else {
            mx[0] = fmaxf(mx[0], g_als[i]);
        }
    }
#pragma unroll
    for (int hh = 0; hh < H; hh++)
#pragma unroll
        for (int o = 16; o > 0; o >>= 1)
            mx[hh] = fmaxf(mx[hh], __shfl_xor_sync(0xffffffffu, mx[hh], o));
    __shared__ float sm[8][H > 0 ? H : 1];
    int w = threadIdx.x >> 5, lane = threadIdx.x & 31;
    if (lane == 0)
#pragma unroll
        for (int hh = 0; hh < H; hh++) sm[w][hh] = mx[hh];
    __syncthreads();
    if (threadIdx.x == 0) {
#pragma unroll
        for (int hh = 0; hh < H; hh++) {
            float m = sm[0][hh];
            for (int ww = 1; ww < 8; ww++) m = fmaxf(m, sm[ww][hh]);
            atomicMax(&g_mxals[LAYER][hh], fenc(m));
        }
    }
}

// ---------------- fused segment softmax + weighted aggregate (single edge pass) ----------------
template <int H, int C, bool RELU, int LAYER>
__global__ void k_aggregate(const float* __restrict__ bias, float* __restrict__ outExt, int n) {
    constexpr int D = H * C;
    constexpr int CPL = D / 32;
    constexpr int G = 32 / H;
    float* __restrict__ out = outExt ? outExt : g_act;
    int wid = threadIdx.x >> 5;
    int lane = threadIdx.x & 31;
    int node = blockIdx.x * 4 + wid;
    if (node >= n) return;

    int s0 = g_rowptr[node];
    int s1 = g_rowptr[node + 1];

    int c0 = lane * CPL;
    int hd = lane / G;
    float myald = g_ald[(size_t)node * H + hd];
    // shift = leaky(global_max_als + ald) >= per-dst max of leaky(als+ald); exact softmax shift
    float Mh = fdec(g_mxals[LAYER][hd]);
    float mymx = Mh + myald;
    mymx = (mymx > 0.f) ? mymx : SLOPE * mymx;

    float acc[CPL];
#pragma unroll
    for (int j = 0; j < CPL; j++) acc[j] = 0.f;
    float esum = 0.f;
    for (int i = s0; i < s1; i++) {
        int2 p = g_csr[i];
        float w = __int_as_float(p.y);
        float l = g_als[(size_t)p.x * H + hd] + myald;
        l = (l > 0.f) ? l : SLOPE * l;
        float e = __expf(l - mymx) * w;
        esum += e;
        if (CPL == 4) {
            float4 v = *(const float4*)(g_h + (size_t)p.x * D + c0);
            acc[0] = fmaf(e, v.x, acc[0]);
            acc[1] = fmaf(e, v.y, acc[1]);
            acc[2] = fmaf(e, v.z, acc[2]);
            acc[3] = fmaf(e, v.w, acc[3]);
        } else {
            float2 v = *(const float2*)(g_h + (size_t)p.x * D + c0);
            acc[0] = fmaf(e, v.x, acc[0]);
            acc[1] = fmaf(e, v.y, acc[1]);
        }
    }
    float inv = 1.0f / (esum + 1e-16f);
#pragma unroll
    for (int j = 0; j < CPL; j++) {
        float v = fmaf(acc[j], inv, bias[c0 + j]);
        if (RELU) v = fmaxf(v, 0.f);
        out[(size_t)node * D + c0 + j] = v;
    }
}

// ---------------- host launch ----------------
extern "C" void kernel_launch(void* const* d_in, const int* in_sizes, int n_in,
                              void* d_out, int out_size) {
    const float* x   = (const float*)d_in[0];
    const void*  ei  = d_in[1];
    const float* ew  = (const float*)d_in[2];
    const float* W1  = (const float*)d_in[3];
    const float* aS1 = (const float*)d_in[4];
    const float* aD1 = (const float*)d_in[5];
    const float* b1  = (const float*)d_in[6];
    const float* W2  = (const float*)d_in[7];
    const float* aS2 = (const float*)d_in[8];
    const float* aD2 = (const float*)d_in[9];
    const float* b2  = (const float*)d_in[10];
    const float* W3  = (const float*)d_in[11];
    const float* aS3 = (const float*)d_in[12];
    const float* aD3 = (const float*)d_in[13];
    const float* b3  = (const float*)d_in[14];

    const int E = in_sizes[2];
    const int n = NN;

    // CSR build (reused by all 3 layers); scan2 also inits g_mxals
    k_detect_idx<<<1, 256>>>(ei, E);
    k_zero_deg<<<(n + 255) / 256, 256>>>(n);
    k_count_deg<<<(E + 255) / 256, 256>>>(ei, E, n);
    k_scan1<<<NBLK, SCAN_B>>>(n);
    k_scan2<<<1, 64>>>();
    k_scan3<<<(n + 255) / 256, 256>>>(n);
    k_scatter<<<(E + 255) / 256, 256>>>(ei, ew, E, n);

    const int nodeBlocks = (n + 3) / 4;
    dim3 gemmGrid2(D1 / 64, (n + 127) / 128);
    dim3 gemmGrid1(OUT_F / 64, (n + 127) / 128);

    // Layer 1: 256 -> 128, H=4, C=32, relu
    k_gemm_tf32<<<gemmGrid2, 256>>>(x, W1, n, IN_F, D1);
    k_dots<4, 32><<<nodeBlocks, 128>>>(aS1, aD1, n);
    k_maxals<4, 0><<<128, 256>>>(n);
    k_aggregate<4, 32, true, 0><<<nodeBlocks, 128>>>(b1, nullptr, n);

    // Layer 2: 128 -> 128, H=4, C=32, relu
    k_gemm_tf32<<<gemmGrid2, 256>>>(nullptr, W2, n, D1, D1);
    k_dots<4, 32><<<nodeBlocks, 128>>>(aS2, aD2, n);
    k_maxals<4, 1><<<128, 256>>>(n);
    k_aggregate<4, 32, true, 1><<<nodeBlocks, 128>>>(b2, nullptr, n);

    // Layer 3: 128 -> 64, H=1, C=64, no relu
    k_gemm_tf32<<<gemmGrid1, 256>>>(nullptr, W3, n, D1, OUT_F);
    k_dots<1, 64><<<nodeBlocks, 128>>>(aS3, aD3, n);
    k_maxals<1, 2><<<128, 256>>>(n);
    k_aggregate<1, 64, false, 2><<<nodeBlocks, 128>>>(b3, (float*)d_out, n);
}